// round 1
// baseline (speedup 1.0000x reference)
#include <cuda_runtime.h>
#include <cstdint>

#define NB 4
#define NT 2048
#define NC 1024
#define NH 16
#define NHS 64

// ---------------- scratch (static device globals; no runtime alloc) --------
__device__ float g_q[(size_t)NB * NH * NT * NHS];
__device__ float g_k[(size_t)NB * NH * NT * NHS];
__device__ float g_v[(size_t)NB * NH * NT * NHS];
__device__ float g_attn[(size_t)NB * NT * NC];

// ---------------- tf32 helpers ---------------------------------------------
__device__ __forceinline__ uint32_t f2tf(float x) {
    uint32_t r;
    asm("cvt.rna.tf32.f32 %0, %1;" : "=r"(r) : "f"(x));
    return r;
}

// split x into tf32 hi + tf32 lo (x - hi exact in fp32; lo captures next 11 bits)
__device__ __forceinline__ void split2(float x, uint32_t& h, uint32_t& l) {
    h = f2tf(x);
    l = f2tf(x - __uint_as_float(h));
}

__device__ __forceinline__ void mma8(float* d, const uint32_t* a, uint32_t b0, uint32_t b1) {
    asm volatile(
        "mma.sync.aligned.m16n8k8.row.col.f32.tf32.tf32.f32 "
        "{%0,%1,%2,%3}, {%4,%5,%6,%7}, {%8,%9}, {%0,%1,%2,%3};"
        : "+f"(d[0]), "+f"(d[1]), "+f"(d[2]), "+f"(d[3])
        : "r"(a[0]), "r"(a[1]), "r"(a[2]), "r"(a[3]), "r"(b0), "r"(b1));
}

// ---------------- GEMM: C = A(MxK) * B(NxK)^T, 3xTF32 ----------------------
// MODE 0: QKV projection. A = x. B selected from Wq/Wk/Wv by n-block.
//         Output scattered to g_q/g_k/g_v as [B,H,T,HS].
// MODE 1: out projection. A = g_attn [8192,1024]. B = Wo. Out = d_out + bias.
template <int MODE>
__global__ void __launch_bounds__(256) gemm_nt_kernel(
    const float* __restrict__ A,
    const float* __restrict__ W0, const float* __restrict__ W1,
    const float* __restrict__ W2,
    const float* __restrict__ bias, float* __restrict__ Out)
{
    __shared__ float As[128][36];  // stride 36: bank = (4g+tg), conflict-free frags
    __shared__ float Bs[128][36];

    const int tid  = threadIdx.x;
    const int warp = tid >> 5, lane = tid & 31;
    const int g    = lane >> 2, tg = lane & 3;
    const int wm   = warp >> 2, wn = warp & 3;   // 2 x 4 warp grid, warp tile 64x32
    const int m0   = blockIdx.y * 128;
    const int nb   = blockIdx.x;

    const float* Ap = (MODE == 0) ? A : (const float*)g_attn;
    const float* Bp;
    int n0;
    int sel = 0;
    if (MODE == 0) {
        sel = nb >> 3;
        Bp  = (sel == 0) ? W0 : (sel == 1) ? W1 : W2;
        n0  = (nb & 7) * 128;
    } else {
        Bp = W0;
        n0 = nb * 128;
    }

    float acc[4][4][4];
#pragma unroll
    for (int a = 0; a < 4; a++)
#pragma unroll
        for (int b = 0; b < 4; b++)
#pragma unroll
            for (int c = 0; c < 4; c++) acc[a][b][c] = 0.f;

    const int lr = tid >> 3;         // 0..31
    const int lc = (tid & 7) << 2;   // 0,4,...,28

    for (int kt = 0; kt < NC; kt += 32) {
#pragma unroll
        for (int i = 0; i < 4; i++) {
            int r = lr + i * 32;
            *(float4*)&As[r][lc] = *(const float4*)(Ap + (size_t)(m0 + r) * NC + kt + lc);
            *(float4*)&Bs[r][lc] = *(const float4*)(Bp + (size_t)(n0 + r) * NC + kt + lc);
        }
        __syncthreads();

#pragma unroll
        for (int ks = 0; ks < 4; ks++) {
            const int k0 = ks * 8;
            uint32_t ah[4][4], al[4][4];
#pragma unroll
            for (int mt = 0; mt < 4; mt++) {
                const int r = wm * 64 + mt * 16;
                split2(As[r + g][k0 + tg],         ah[mt][0], al[mt][0]);
                split2(As[r + g + 8][k0 + tg],     ah[mt][1], al[mt][1]);
                split2(As[r + g][k0 + tg + 4],     ah[mt][2], al[mt][2]);
                split2(As[r + g + 8][k0 + tg + 4], ah[mt][3], al[mt][3]);
            }
#pragma unroll
            for (int nt = 0; nt < 4; nt++) {
                const int cb = wn * 32 + nt * 8;
                uint32_t b0h, b0l, b1h, b1l;
                split2(Bs[cb + g][k0 + tg],     b0h, b0l);
                split2(Bs[cb + g][k0 + tg + 4], b1h, b1l);
#pragma unroll
                for (int mt = 0; mt < 4; mt++) {
                    mma8(acc[mt][nt], ah[mt], b0h, b1h);
                    mma8(acc[mt][nt], al[mt], b0h, b1h);
                    mma8(acc[mt][nt], ah[mt], b0l, b1l);
                }
            }
        }
        __syncthreads();
    }

    // epilogue
    float* dst = nullptr;
    if (MODE == 0) dst = (sel == 0) ? g_q : (sel == 1) ? g_k : g_v;

#pragma unroll
    for (int mt = 0; mt < 4; mt++) {
        int row = m0 + wm * 64 + mt * 16 + g;
#pragma unroll
        for (int nt = 0; nt < 4; nt++) {
            int col = n0 + wn * 32 + nt * 8 + 2 * tg;
            if (MODE == 0) {
                int bb = row >> 11, t = row & (NT - 1);
                int hh = col >> 6,  d = col & 63;
                float* p = dst + (((size_t)(bb * NH + hh) * NT + t) * NHS) + d;
                *(float2*)p              = make_float2(acc[mt][nt][0], acc[mt][nt][1]);
                *(float2*)(p + 8 * NHS)  = make_float2(acc[mt][nt][2], acc[mt][nt][3]);
            } else {
                float2 bv = *(const float2*)(bias + col);
                *(float2*)(Out + (size_t)row * NC + col) =
                    make_float2(acc[mt][nt][0] + bv.x, acc[mt][nt][1] + bv.y);
                *(float2*)(Out + (size_t)(row + 8) * NC + col) =
                    make_float2(acc[mt][nt][2] + bv.x, acc[mt][nt][3] + bv.y);
            }
        }
    }
}

// ---------------- flash attention (causal, scale = +sqrt(HS) = 8) ----------
// Grid: (T/64, B*H). 128 threads = 4 warps; warp w owns S rows [w*16, w*16+16).
// K/V consumed in 32-key steps. Both GEMMs 3xTF32. P round-trips via a
// per-warp-private smem tile (rows w*16.. only -> __syncwarp suffices).
__global__ void __launch_bounds__(128) flash_attn_kernel()
{
    __shared__ float Qs[64][68];
    __shared__ float Ks[32][68];
    __shared__ float Vs[32][68];
    __shared__ float Ps[64][36];

    const int tid  = threadIdx.x;
    const int warp = tid >> 5, lane = tid & 31;
    const int g    = lane >> 2, tg = lane & 3;
    const int qi   = blockIdx.x, bh = blockIdx.y;

    const size_t base = (size_t)bh * NT * NHS;
    const float* Qg = g_q + base + (size_t)qi * 64 * NHS;
    const float* Kg = g_k + base;
    const float* Vg = g_v + base;

    // load Q tile once, pre-scaled by sqrt(HS)=8 (exact power of 2)
    for (int i = tid; i < 64 * 16; i += 128) {
        int r = i >> 4, c4 = (i & 15) << 2;
        float4 v = *(const float4*)(Qg + r * 64 + c4);
        v.x *= 8.f; v.y *= 8.f; v.z *= 8.f; v.w *= 8.f;
        *(float4*)&Qs[r][c4] = v;
    }

    float o[8][4];
#pragma unroll
    for (int i = 0; i < 8; i++)
#pragma unroll
        for (int j = 0; j < 4; j++) o[i][j] = 0.f;
    float mr[2] = {-1e30f, -1e30f};
    float lr[2] = {0.f, 0.f};

    const int row0 = qi * 64 + warp * 16 + g;
    const int nkt  = 2 * qi + 2;

    for (int kt = 0; kt < nkt; kt++) {
        __syncthreads();  // protect Ks/Vs reuse across warps
        for (int i = tid; i < 32 * 16; i += 128) {
            int r = i >> 4, c4 = (i & 15) << 2;
            *(float4*)&Ks[r][c4] = *(const float4*)(Kg + (size_t)(kt * 32 + r) * 64 + c4);
            *(float4*)&Vs[r][c4] = *(const float4*)(Vg + (size_t)(kt * 32 + r) * 64 + c4);
        }
        __syncthreads();

        // S = Q * K^T  (64x32 per CTA, 16x32 per warp)
        float s[4][4];
#pragma unroll
        for (int i = 0; i < 4; i++)
#pragma unroll
            for (int j = 0; j < 4; j++) s[i][j] = 0.f;

#pragma unroll
        for (int ks = 0; ks < 8; ks++) {
            const int k0 = ks * 8;
            const int r  = warp * 16;
            uint32_t ah[4], al[4];
            split2(Qs[r + g][k0 + tg],         ah[0], al[0]);
            split2(Qs[r + g + 8][k0 + tg],     ah[1], al[1]);
            split2(Qs[r + g][k0 + tg + 4],     ah[2], al[2]);
            split2(Qs[r + g + 8][k0 + tg + 4], ah[3], al[3]);
#pragma unroll
            for (int nt = 0; nt < 4; nt++) {
                uint32_t b0h, b0l, b1h, b1l;
                split2(Ks[nt * 8 + g][k0 + tg],     b0h, b0l);
                split2(Ks[nt * 8 + g][k0 + tg + 4], b1h, b1l);
                mma8(s[nt], ah, b0h, b1h);
                mma8(s[nt], al, b0h, b1h);
                mma8(s[nt], ah, b0l, b1l);
            }
        }

        // causal mask (only the two diagonal-adjacent tiles need it)
        if (kt >= 2 * qi) {
#pragma unroll
            for (int nt = 0; nt < 4; nt++)
#pragma unroll
                for (int c = 0; c < 4; c++) {
                    int key = kt * 32 + nt * 8 + 2 * tg + (c & 1);
                    int rr  = row0 + ((c & 2) ? 8 : 0);
                    if (key > rr) s[nt][c] = -1e30f;
                }
        }

        // online softmax update (rows g and g+8 per thread)
#pragma unroll
        for (int r = 0; r < 2; r++) {
            const int cb = 2 * r;
            float mx = mr[r];
#pragma unroll
            for (int nt = 0; nt < 4; nt++)
                mx = fmaxf(mx, fmaxf(s[nt][cb], s[nt][cb + 1]));
            mx = fmaxf(mx, __shfl_xor_sync(0xffffffffu, mx, 1));
            mx = fmaxf(mx, __shfl_xor_sync(0xffffffffu, mx, 2));

            float alpha = __expf(mr[r] - mx);
            float rs = 0.f;
#pragma unroll
            for (int nt = 0; nt < 4; nt++) {
                float p0 = __expf(s[nt][cb] - mx);
                float p1 = __expf(s[nt][cb + 1] - mx);
                s[nt][cb] = p0; s[nt][cb + 1] = p1;
                rs += p0 + p1;
            }
            rs += __shfl_xor_sync(0xffffffffu, rs, 1);
            rs += __shfl_xor_sync(0xffffffffu, rs, 2);
            lr[r] = lr[r] * alpha + rs;
            mr[r] = mx;
#pragma unroll
            for (int nt = 0; nt < 8; nt++) {
                o[nt][cb]     *= alpha;
                o[nt][cb + 1] *= alpha;
            }
        }

        // stage P in smem (warp-private rows -> only __syncwarp needed)
#pragma unroll
        for (int nt = 0; nt < 4; nt++) {
            int col = nt * 8 + 2 * tg;
            Ps[warp * 16 + g][col]         = s[nt][0];
            Ps[warp * 16 + g][col + 1]     = s[nt][1];
            Ps[warp * 16 + g + 8][col]     = s[nt][2];
            Ps[warp * 16 + g + 8][col + 1] = s[nt][3];
        }
        __syncwarp();

        // O += P * V  (k over 32 keys, n over 64 head dims)
#pragma unroll
        for (int ks = 0; ks < 4; ks++) {
            const int k0 = ks * 8;
            const int r  = warp * 16;
            uint32_t ah[4], al[4];
            split2(Ps[r + g][k0 + tg],         ah[0], al[0]);
            split2(Ps[r + g + 8][k0 + tg],     ah[1], al[1]);
            split2(Ps[r + g][k0 + tg + 4],     ah[2], al[2]);
            split2(Ps[r + g + 8][k0 + tg + 4], ah[3], al[3]);
#pragma unroll
            for (int nt = 0; nt < 8; nt++) {
                uint32_t b0h, b0l, b1h, b1l;
                split2(Vs[k0 + tg][nt * 8 + g],     b0h, b0l);
                split2(Vs[k0 + tg + 4][nt * 8 + g], b1h, b1l);
                mma8(o[nt], ah, b0h, b1h);
                mma8(o[nt], al, b0h, b1h);
                mma8(o[nt], ah, b0l, b1l);
            }
        }
    }

    // normalize + write [B, T, H*HS] so the out-projection is a plain NT GEMM
    const int bb = bh >> 4;     // / NH
    const int hh = bh & 15;     // % NH
    const float inv0 = 1.f / lr[0];
    const float inv1 = 1.f / lr[1];
#pragma unroll
    for (int nt = 0; nt < 8; nt++) {
        int col = hh * 64 + nt * 8 + 2 * tg;
        size_t a0 = (size_t)(bb * NT + row0) * NC + col;
        *(float2*)&g_attn[a0]           = make_float2(o[nt][0] * inv0, o[nt][1] * inv0);
        *(float2*)&g_attn[a0 + 8 * NC]  = make_float2(o[nt][2] * inv1, o[nt][3] * inv1);
    }
}

// ---------------- launcher --------------------------------------------------
extern "C" void kernel_launch(void* const* d_in, const int* in_sizes, int n_in,
                              void* d_out, int out_size)
{
    const float* x  = (const float*)d_in[0];
    const float* Wq = (const float*)d_in[1];
    const float* Wk = (const float*)d_in[2];
    const float* Wv = (const float*)d_in[3];
    const float* Wo = (const float*)d_in[4];
    const float* bo = (const float*)d_in[5];
    float* out = (float*)d_out;

    // 1) fused QKV projection -> g_q/g_k/g_v  [B,H,T,HS]
    gemm_nt_kernel<0><<<dim3(24, 64), 256>>>(x, Wq, Wk, Wv, nullptr, nullptr);
    // 2) causal flash attention -> g_attn [B,T,C]
    flash_attn_kernel<<<dim3(NT / 64, NB * NH), 128>>>();
    // 3) output projection + bias -> d_out
    gemm_nt_kernel<1><<<dim3(8, 64), 256>>>(nullptr, Wo, nullptr, nullptr, bo, out);
}

// round 2
// speedup vs baseline: 1.3863x; 1.3863x over previous
#include <cuda_runtime.h>
#include <cstdint>

#define NB 4
#define NT 2048
#define NC 1024
#define NH 16
#define NHS 64

// ---------------- scratch (static device globals; no runtime alloc) --------
__device__ float g_q[(size_t)NB * NH * NT * NHS];
__device__ float g_k[(size_t)NB * NH * NT * NHS];
__device__ float g_v[(size_t)NB * NH * NT * NHS];
__device__ float g_attn[(size_t)NB * NT * NC];

// ---------------- tf32 helpers ---------------------------------------------
__device__ __forceinline__ uint32_t f2tf(float x) {
    uint32_t r;
    asm("cvt.rna.tf32.f32 %0, %1;" : "=r"(r) : "f"(x));
    return r;
}
__device__ __forceinline__ float tf32r(float x) { return __uint_as_float(f2tf(x)); }

// split x -> tf32 hi + tf32 lo, stored to smem
__device__ __forceinline__ void split_store(float x, float* ph, float* pl) {
    float h = tf32r(x);
    *ph = h;
    *pl = tf32r(x - h);
}
// split in registers (for P which is produced, not loaded)
__device__ __forceinline__ void split2(float x, uint32_t& h, uint32_t& l) {
    h = f2tf(x);
    l = f2tf(x - __uint_as_float(h));
}
__device__ __forceinline__ uint32_t fb(float x) { return __float_as_uint(x); }

__device__ __forceinline__ void mma8(float* d, const uint32_t* a, uint32_t b0, uint32_t b1) {
    asm volatile(
        "mma.sync.aligned.m16n8k8.row.col.f32.tf32.tf32.f32 "
        "{%0,%1,%2,%3}, {%4,%5,%6,%7}, {%8,%9}, {%0,%1,%2,%3};"
        : "+f"(d[0]), "+f"(d[1]), "+f"(d[2]), "+f"(d[3])
        : "r"(a[0]), "r"(a[1]), "r"(a[2]), "r"(a[3]), "r"(b0), "r"(b1));
}

// ---------------- GEMM: C = A(MxK) * B(NxK)^T ------------------------------
// MODE 0 (QKV proj): 3xTF32 (score path, softmax-amplified). Scatter to q/k/v.
// MODE 1 (out proj): 2xTF32 (linear error path). Out = A*Wo^T + bias.
// Pre-split hi/lo smem tiles + register-prefetch double buffering.
template <int MODE>
__global__ void __launch_bounds__(256) gemm_nt_kernel(
    const float* __restrict__ A,
    const float* __restrict__ W0, const float* __restrict__ W1,
    const float* __restrict__ W2,
    const float* __restrict__ bias, float* __restrict__ Out)
{
    extern __shared__ float sm[];
    float (*Ah)[36] = (float(*)[36])(sm);
    float (*Al)[36] = (float(*)[36])(sm + 4608);
    float (*Bh)[36] = (float(*)[36])(sm + 9216);
    float (*Bl)[36] = (float(*)[36])(sm + 13824);

    const int tid  = threadIdx.x;
    const int warp = tid >> 5, lane = tid & 31;
    const int g    = lane >> 2, tg = lane & 3;
    const int wm   = warp >> 2, wn = warp & 3;   // 2 x 4 warps, warp tile 64x32
    const int m0   = blockIdx.y * 128;
    const int nb   = blockIdx.x;

    const float* Ap = (MODE == 0) ? A : (const float*)g_attn;
    const float* Bp;
    int n0, sel = 0;
    if (MODE == 0) {
        sel = nb >> 3;
        Bp  = (sel == 0) ? W0 : (sel == 1) ? W1 : W2;
        n0  = (nb & 7) * 128;
    } else {
        Bp = W0;
        n0 = nb * 128;
    }

    float acc[4][4][4];
#pragma unroll
    for (int a = 0; a < 4; a++)
#pragma unroll
        for (int b = 0; b < 4; b++)
#pragma unroll
            for (int c = 0; c < 4; c++) acc[a][b][c] = 0.f;

    const int lr = tid >> 3;        // 0..31
    const int lc = (tid & 7) << 2;  // 0,4,...,28

    float4 ra[4], rb[4];
#pragma unroll
    for (int i = 0; i < 4; i++) {
        ra[i] = *(const float4*)(Ap + (size_t)(m0 + lr + i * 32) * NC + lc);
        rb[i] = *(const float4*)(Bp + (size_t)(n0 + lr + i * 32) * NC + lc);
    }

    for (int kt = 0; kt < NC; kt += 32) {
        __syncthreads();
        // store prefetched regs -> smem, splitting hi/lo once per element
#pragma unroll
        for (int i = 0; i < 4; i++) {
            int r = lr + i * 32;
            const float* pa = (const float*)&ra[i];
            const float* pb = (const float*)&rb[i];
#pragma unroll
            for (int e = 0; e < 4; e++) {
                split_store(pa[e], &Ah[r][lc + e], &Al[r][lc + e]);
                if (MODE == 0) split_store(pb[e], &Bh[r][lc + e], &Bl[r][lc + e]);
                else           Bh[r][lc + e] = tf32r(pb[e]);
            }
        }
        __syncthreads();
        // prefetch next tile into registers (overlaps with mma below)
        if (kt + 32 < NC) {
#pragma unroll
            for (int i = 0; i < 4; i++) {
                ra[i] = *(const float4*)(Ap + (size_t)(m0 + lr + i * 32) * NC + kt + 32 + lc);
                rb[i] = *(const float4*)(Bp + (size_t)(n0 + lr + i * 32) * NC + kt + 32 + lc);
            }
        }

#pragma unroll
        for (int ks = 0; ks < 4; ks++) {
            const int k0 = ks * 8;
            uint32_t ah[4][4], al[4][4];
#pragma unroll
            for (int mt = 0; mt < 4; mt++) {
                const int r = wm * 64 + mt * 16;
                ah[mt][0] = fb(Ah[r + g][k0 + tg]);         al[mt][0] = fb(Al[r + g][k0 + tg]);
                ah[mt][1] = fb(Ah[r + g + 8][k0 + tg]);     al[mt][1] = fb(Al[r + g + 8][k0 + tg]);
                ah[mt][2] = fb(Ah[r + g][k0 + tg + 4]);     al[mt][2] = fb(Al[r + g][k0 + tg + 4]);
                ah[mt][3] = fb(Ah[r + g + 8][k0 + tg + 4]); al[mt][3] = fb(Al[r + g + 8][k0 + tg + 4]);
            }
#pragma unroll
            for (int nt = 0; nt < 4; nt++) {
                const int cb = wn * 32 + nt * 8;
                uint32_t b0h = fb(Bh[cb + g][k0 + tg]);
                uint32_t b1h = fb(Bh[cb + g][k0 + tg + 4]);
                uint32_t b0l = 0, b1l = 0;
                if (MODE == 0) {
                    b0l = fb(Bl[cb + g][k0 + tg]);
                    b1l = fb(Bl[cb + g][k0 + tg + 4]);
                }
#pragma unroll
                for (int mt = 0; mt < 4; mt++) {
                    mma8(acc[mt][nt], ah[mt], b0h, b1h);
                    mma8(acc[mt][nt], al[mt], b0h, b1h);
                    if (MODE == 0) mma8(acc[mt][nt], ah[mt], b0l, b1l);
                }
            }
        }
    }

    // epilogue
    float* dst = nullptr;
    if (MODE == 0) dst = (sel == 0) ? g_q : (sel == 1) ? g_k : g_v;

#pragma unroll
    for (int mt = 0; mt < 4; mt++) {
        int row = m0 + wm * 64 + mt * 16 + g;
#pragma unroll
        for (int nt = 0; nt < 4; nt++) {
            int col = n0 + wn * 32 + nt * 8 + 2 * tg;
            if (MODE == 0) {
                int bb = row >> 11, t = row & (NT - 1);
                int hh = col >> 6,  d = col & 63;
                float* p = dst + (((size_t)(bb * NH + hh) * NT + t) * NHS) + d;
                *(float2*)p             = make_float2(acc[mt][nt][0], acc[mt][nt][1]);
                *(float2*)(p + 8 * NHS) = make_float2(acc[mt][nt][2], acc[mt][nt][3]);
            } else {
                float2 bv = *(const float2*)(bias + col);
                *(float2*)(Out + (size_t)row * NC + col) =
                    make_float2(acc[mt][nt][0] + bv.x, acc[mt][nt][1] + bv.y);
                *(float2*)(Out + (size_t)(row + 8) * NC + col) =
                    make_float2(acc[mt][nt][2] + bv.x, acc[mt][nt][3] + bv.y);
            }
        }
    }
}

// ---------------- flash attention (causal, scale = +sqrt(HS) = 8) ----------
// Grid: (T/128, B*H). 256 threads = 8 warps; warp w owns rows [16w, 16w+16).
// K/V in 32-key steps, register-prefetched. Q/K pre-split hi/lo in smem
// (3xTF32 scores); V hi-only (2xTF32 PV, linear error path).
__global__ void __launch_bounds__(256) flash_attn_kernel()
{
    extern __shared__ float sm[];
    float (*Qh)[68] = (float(*)[68])(sm);
    float (*Ql)[68] = (float(*)[68])(sm + 8704);
    float (*Kh)[68] = (float(*)[68])(sm + 17408);
    float (*Kl)[68] = (float(*)[68])(sm + 19584);
    float (*Vh)[72] = (float(*)[72])(sm + 21760);
    float (*Ps)[36] = (float(*)[36])(sm + 24064);

    const int tid  = threadIdx.x;
    const int warp = tid >> 5, lane = tid & 31;
    const int g    = lane >> 2, tg = lane & 3;
    const int qi   = blockIdx.x, bh = blockIdx.y;

    const size_t base = (size_t)bh * NT * NHS;
    const float* Qg = g_q + base + (size_t)qi * 128 * NHS;
    const float* Kg = g_k + base;
    const float* Vg = g_v + base;

    // load Q tile once, pre-scaled by sqrt(HS)=8 (exact pow2), pre-split
    for (int i = tid; i < 128 * 16; i += 256) {
        int r = i >> 4, c4 = (i & 15) << 2;
        float4 v = *(const float4*)(Qg + r * 64 + c4);
        split_store(v.x * 8.f, &Qh[r][c4],     &Ql[r][c4]);
        split_store(v.y * 8.f, &Qh[r][c4 + 1], &Ql[r][c4 + 1]);
        split_store(v.z * 8.f, &Qh[r][c4 + 2], &Ql[r][c4 + 2]);
        split_store(v.w * 8.f, &Qh[r][c4 + 3], &Ql[r][c4 + 3]);
    }

    float o[8][4];
#pragma unroll
    for (int i = 0; i < 8; i++)
#pragma unroll
        for (int j = 0; j < 4; j++) o[i][j] = 0.f;
    float mr[2]   = {-1e30f, -1e30f};
    float lsum[2] = {0.f, 0.f};

    const int row0 = qi * 128 + warp * 16 + g;
    const int nkt  = 4 * qi + 4;

    float4 rk[2], rv[2];
#pragma unroll
    for (int j = 0; j < 2; j++) {
        int idx = tid + j * 256;
        int r = idx >> 4, c4 = (idx & 15) << 2;
        rk[j] = *(const float4*)(Kg + (size_t)r * 64 + c4);
        rv[j] = *(const float4*)(Vg + (size_t)r * 64 + c4);
    }

    for (int kt = 0; kt < nkt; kt++) {
        __syncthreads();
        // store prefetched K/V -> smem (split K, round V)
#pragma unroll
        for (int j = 0; j < 2; j++) {
            int idx = tid + j * 256;
            int r = idx >> 4, c4 = (idx & 15) << 2;
            const float* pk = (const float*)&rk[j];
            const float* pv = (const float*)&rv[j];
#pragma unroll
            for (int e = 0; e < 4; e++) {
                split_store(pk[e], &Kh[r][c4 + e], &Kl[r][c4 + e]);
                Vh[r][c4 + e] = tf32r(pv[e]);
            }
        }
        __syncthreads();
        if (kt + 1 < nkt) {
#pragma unroll
            for (int j = 0; j < 2; j++) {
                int idx = tid + j * 256;
                int r = idx >> 4, c4 = (idx & 15) << 2;
                rk[j] = *(const float4*)(Kg + (size_t)((kt + 1) * 32 + r) * 64 + c4);
                rv[j] = *(const float4*)(Vg + (size_t)((kt + 1) * 32 + r) * 64 + c4);
            }
        }

        // warp-level skip of fully-masked key blocks (uniform per warp)
        if (kt * 32 > qi * 128 + warp * 16 + 15) continue;

        // S = Q * K^T  (16x32 per warp), 3xTF32
        float s[4][4];
#pragma unroll
        for (int i = 0; i < 4; i++)
#pragma unroll
            for (int j = 0; j < 4; j++) s[i][j] = 0.f;

#pragma unroll
        for (int ks = 0; ks < 8; ks++) {
            const int k0 = ks * 8, r = warp * 16;
            uint32_t qh_[4], ql_[4];
            qh_[0] = fb(Qh[r + g][k0 + tg]);         ql_[0] = fb(Ql[r + g][k0 + tg]);
            qh_[1] = fb(Qh[r + g + 8][k0 + tg]);     ql_[1] = fb(Ql[r + g + 8][k0 + tg]);
            qh_[2] = fb(Qh[r + g][k0 + tg + 4]);     ql_[2] = fb(Ql[r + g][k0 + tg + 4]);
            qh_[3] = fb(Qh[r + g + 8][k0 + tg + 4]); ql_[3] = fb(Ql[r + g + 8][k0 + tg + 4]);
#pragma unroll
            for (int nt = 0; nt < 4; nt++) {
                uint32_t kh0 = fb(Kh[nt * 8 + g][k0 + tg]);
                uint32_t kh1 = fb(Kh[nt * 8 + g][k0 + tg + 4]);
                uint32_t kl0 = fb(Kl[nt * 8 + g][k0 + tg]);
                uint32_t kl1 = fb(Kl[nt * 8 + g][k0 + tg + 4]);
                mma8(s[nt], qh_, kh0, kh1);
                mma8(s[nt], ql_, kh0, kh1);
                mma8(s[nt], qh_, kl0, kl1);
            }
        }

        // causal mask (only when this block can touch the diagonal)
        if (kt * 32 + 31 > qi * 128 + warp * 16) {
#pragma unroll
            for (int nt = 0; nt < 4; nt++)
#pragma unroll
                for (int c = 0; c < 4; c++) {
                    int key = kt * 32 + nt * 8 + 2 * tg + (c & 1);
                    int rr  = row0 + ((c & 2) ? 8 : 0);
                    if (key > rr) s[nt][c] = -1e30f;
                }
        }

        // online softmax (rows g and g+8)
#pragma unroll
        for (int r = 0; r < 2; r++) {
            const int cb = 2 * r;
            float mx = mr[r];
#pragma unroll
            for (int nt = 0; nt < 4; nt++)
                mx = fmaxf(mx, fmaxf(s[nt][cb], s[nt][cb + 1]));
            mx = fmaxf(mx, __shfl_xor_sync(0xffffffffu, mx, 1));
            mx = fmaxf(mx, __shfl_xor_sync(0xffffffffu, mx, 2));

            float alpha = __expf(mr[r] - mx);
            float rs = 0.f;
#pragma unroll
            for (int nt = 0; nt < 4; nt++) {
                float p0 = __expf(s[nt][cb] - mx);
                float p1 = __expf(s[nt][cb + 1] - mx);
                s[nt][cb] = p0; s[nt][cb + 1] = p1;
                rs += p0 + p1;
            }
            rs += __shfl_xor_sync(0xffffffffu, rs, 1);
            rs += __shfl_xor_sync(0xffffffffu, rs, 2);
            lsum[r] = lsum[r] * alpha + rs;
            mr[r]   = mx;
#pragma unroll
            for (int nt = 0; nt < 8; nt++) {
                o[nt][cb]     *= alpha;
                o[nt][cb + 1] *= alpha;
            }
        }

        // stage P (warp-private rows -> __syncwarp only)
#pragma unroll
        for (int nt = 0; nt < 4; nt++) {
            int col = nt * 8 + 2 * tg;
            Ps[warp * 16 + g][col]         = s[nt][0];
            Ps[warp * 16 + g][col + 1]     = s[nt][1];
            Ps[warp * 16 + g + 8][col]     = s[nt][2];
            Ps[warp * 16 + g + 8][col + 1] = s[nt][3];
        }
        __syncwarp();

        // O += P * V : 2xTF32 (P split, V rounded)
#pragma unroll
        for (int ks = 0; ks < 4; ks++) {
            const int k0 = ks * 8, r = warp * 16;
            uint32_t ah_[4], al_[4];
            split2(Ps[r + g][k0 + tg],         ah_[0], al_[0]);
            split2(Ps[r + g + 8][k0 + tg],     ah_[1], al_[1]);
            split2(Ps[r + g][k0 + tg + 4],     ah_[2], al_[2]);
            split2(Ps[r + g + 8][k0 + tg + 4], ah_[3], al_[3]);
#pragma unroll
            for (int nt = 0; nt < 8; nt++) {
                uint32_t v0 = fb(Vh[k0 + tg][nt * 8 + g]);
                uint32_t v1 = fb(Vh[k0 + tg + 4][nt * 8 + g]);
                mma8(o[nt], ah_, v0, v1);
                mma8(o[nt], al_, v0, v1);
            }
        }
    }

    // normalize + write [B, T, H*HS]
    const int bb = bh >> 4;
    const int hh = bh & 15;
    const float inv0 = 1.f / lsum[0];
    const float inv1 = 1.f / lsum[1];
#pragma unroll
    for (int nt = 0; nt < 8; nt++) {
        int col = hh * 64 + nt * 8 + 2 * tg;
        size_t a0 = (size_t)(bb * NT + row0) * NC + col;
        *(float2*)&g_attn[a0]          = make_float2(o[nt][0] * inv0, o[nt][1] * inv0);
        *(float2*)&g_attn[a0 + 8 * NC] = make_float2(o[nt][2] * inv1, o[nt][3] * inv1);
    }
}

// ---------------- launcher --------------------------------------------------
extern "C" void kernel_launch(void* const* d_in, const int* in_sizes, int n_in,
                              void* d_out, int out_size)
{
    const float* x  = (const float*)d_in[0];
    const float* Wq = (const float*)d_in[1];
    const float* Wk = (const float*)d_in[2];
    const float* Wv = (const float*)d_in[3];
    const float* Wo = (const float*)d_in[4];
    const float* bo = (const float*)d_in[5];
    float* out = (float*)d_out;

    const int smem_gemm  = 4 * 128 * 36 * 4;  // 73728 B
    const int smem_flash = (2 * 128 * 68 + 2 * 32 * 68 + 32 * 72 + 128 * 36) * 4;  // 114688 B

    cudaFuncSetAttribute(gemm_nt_kernel<0>, cudaFuncAttributeMaxDynamicSharedMemorySize, smem_gemm);
    cudaFuncSetAttribute(gemm_nt_kernel<1>, cudaFuncAttributeMaxDynamicSharedMemorySize, smem_gemm);
    cudaFuncSetAttribute(flash_attn_kernel, cudaFuncAttributeMaxDynamicSharedMemorySize, smem_flash);

    // 1) fused QKV projection -> g_q/g_k/g_v  [B,H,T,HS]
    gemm_nt_kernel<0><<<dim3(24, 64), 256, smem_gemm>>>(x, Wq, Wk, Wv, nullptr, nullptr);
    // 2) causal flash attention -> g_attn [B,T,C]
    flash_attn_kernel<<<dim3(NT / 128, NB * NH), 256, smem_flash>>>();
    // 3) output projection + bias -> d_out
    gemm_nt_kernel<1><<<dim3(8, 64), 256, smem_gemm>>>(nullptr, Wo, nullptr, nullptr, bo, out);
}